// round 13
// baseline (speedup 1.0000x reference)
#include <cuda_runtime.h>
#include <cuda_bf16.h>
#include <math.h>

// Problem dims
#define BB 1024
#define TT 512
#define FF 64
#define HH 128
#define GG 384   // 3*H, gate order (r, z, n)

__device__ __forceinline__ float sigmoid_fast(float x) {
    return __fdividef(1.f, 1.f + __expf(-x));
}
__device__ __forceinline__ float tanh_fast(float x) {
    return 1.f - __fdividef(2.f, __expf(2.f * x) + 1.f);
}

// cp.async helpers (16B)
__device__ __forceinline__ void cp_async16(unsigned int smem_addr, const void* gptr) {
    asm volatile("cp.async.cg.shared.global [%0], [%1], 16;" :: "r"(smem_addr), "l"(gptr));
}
__device__ __forceinline__ void cp_commit() {
    asm volatile("cp.async.commit_group;");
}
__device__ __forceinline__ void cp_wait_all() {
    asm volatile("cp.async.wait_group 0;" ::: "memory");
}

// bf16 mma m16n8k16 row.col, f32 accumulate
__device__ __forceinline__ void mma_bf16(float* c, const unsigned* a, const unsigned* b) {
    asm volatile(
        "mma.sync.aligned.m16n8k16.row.col.f32.bf16.bf16.f32 "
        "{%0,%1,%2,%3}, {%4,%5,%6,%7}, {%8,%9}, {%0,%1,%2,%3};"
        : "+f"(c[0]), "+f"(c[1]), "+f"(c[2]), "+f"(c[3])
        : "r"(a[0]), "r"(a[1]), "r"(a[2]), "r"(a[3]), "r"(b[0]), "r"(b[1]));
}

__device__ __forceinline__ unsigned pack_bf16(float f0, float f1) {
    unsigned short u0 = __bfloat16_as_ushort(__float2bfloat16(f0));
    unsigned short u1 = __bfloat16_as_ushort(__float2bfloat16(f1));
    return (unsigned)u0 | ((unsigned)u1 << 16);
}

__device__ __forceinline__ float bf16_res(float v) {   // v - bf16(v)
    return v - __bfloat162float(__float2bfloat16(v));
}

// Scratch (allocation-free rule: __device__ globals)
__device__ float g_xg[(size_t)BB * TT * GG];  // [B*T, 3H] input-side pre-acts (includes b_ih)
__device__ float g_hT[BB * HH];               // final hidden state

extern __shared__ __align__(16) char g_dsmem[];

#define HGS 388                  // padded f32 row stride (frag-store tiles)

// ---------------------------------------------------------------------------
// Kernel A: xg = x @ W_ih^T + b_ih on tensor cores (unchanged from R9 pass).
// ---------------------------------------------------------------------------
#define XNT (BB * TT / 16)       // 32768 tiles
#define X_THREADS 512
#define X_BLOCKS 148
#define WPAD 72                  // padded bf16 K-stride

#define X_OFF_WLO 0
#define X_SZ_WLO  (GG * WPAD * 2)           // 55296
#define X_OFF_XF  (X_OFF_WLO + X_SZ_WLO)
#define X_SZ_XF   (2 * 16 * FF * 4)         // 8192
#define X_OFF_XHI (X_OFF_XF + X_SZ_XF)
#define X_SZ_XB   (2 * 16 * WPAD * 2)       // 4608
#define X_OFF_XLO (X_OFF_XHI + X_SZ_XB)
#define X_OFF_HG  (X_OFF_XLO + X_SZ_XB)
#define X_SZ_HG   (16 * HGS * 4)            // 24832
#define X_OFF_BS  (X_OFF_HG + X_SZ_HG)
#define X_SZ_BS   (GG * 4)
#define X_SMEM    (X_OFF_BS + X_SZ_BS)      // 99072 B

__global__ __launch_bounds__(X_THREADS, 1) void xg_mma_kernel(
    const float* __restrict__ x,
    const float* __restrict__ W_ih,
    const float* __restrict__ b_ih)
{
    __nv_bfloat16* Wlo = (__nv_bfloat16*)(g_dsmem + X_OFF_WLO);
    float* Xf = (float*)(g_dsmem + X_OFF_XF);
    __nv_bfloat16* Xhi = (__nv_bfloat16*)(g_dsmem + X_OFF_XHI);
    __nv_bfloat16* Xlo = (__nv_bfloat16*)(g_dsmem + X_OFF_XLO);
    float* HG = (float*)(g_dsmem + X_OFF_HG);
    float* BS = (float*)(g_dsmem + X_OFF_BS);

    const int tid = threadIdx.x;
    const int warp = tid >> 5;
    const int lane = tid & 31;
    const int gid = lane >> 2;
    const int tig = lane & 3;
    const int n0 = warp * 24;

    for (int i = tid; i < GG * FF; i += X_THREADS) {
        int n = i >> 6, k = i & 63;
        float w = W_ih[i];
        Wlo[n * WPAD + k] = __float2bfloat16(bf16_res(w));
    }
    for (int i = tid; i < GG; i += X_THREADS) BS[i] = b_ih[i];

    unsigned bhi[3][4][2];
#pragma unroll
    for (int nt = 0; nt < 3; nt++)
#pragma unroll
        for (int kt = 0; kt < 4; kt++) {
            const float* wr = W_ih + (size_t)(n0 + nt * 8 + gid) * FF + kt * 16 + 2 * tig;
            bhi[nt][kt][0] = pack_bf16(wr[0], wr[1]);
            bhi[nt][kt][1] = pack_bf16(wr[8], wr[9]);
        }

    const unsigned xf_base = (unsigned)__cvta_generic_to_shared(Xf);
    auto stage = [&](int tile, int buf) {
        if (tile < XNT && tid < 256)
            cp_async16(xf_base + (unsigned)buf * 4096u + (unsigned)tid * 16u,
                       (const char*)x + (size_t)tile * 4096 + (size_t)tid * 16);
        cp_commit();
    };

    stage(blockIdx.x, 0);
    cp_wait_all();
    __syncthreads();

    int it = 0;
    for (int tile = blockIdx.x; tile < XNT; tile += gridDim.x, it++) {
        const int buf = it & 1;
        stage(tile + gridDim.x, buf ^ 1);

        for (int i = tid; i < 16 * FF; i += X_THREADS) {
            int r = i >> 6, c = i & 63;
            float v = Xf[buf * 1024 + i];
            __nv_bfloat16 hi = __float2bfloat16(v);
            Xhi[buf * 16 * WPAD + r * WPAD + c] = hi;
            Xlo[buf * 16 * WPAD + r * WPAD + c] =
                __float2bfloat16(v - __bfloat162float(hi));
        }
        __syncthreads();

        float acc[3][4];
#pragma unroll
        for (int nt = 0; nt < 3; nt++)
#pragma unroll
            for (int i = 0; i < 4; i++) acc[nt][i] = 0.f;

        const __nv_bfloat16* XH = Xhi + buf * 16 * WPAD;
        const __nv_bfloat16* XL = Xlo + buf * 16 * WPAD;
#pragma unroll
        for (int kt = 0; kt < 4; kt++) {
            const int col = kt * 16 + 2 * tig;
            unsigned ah[4], al[4];
            ah[0] = *(const unsigned*)(XH + gid * WPAD + col);
            ah[1] = *(const unsigned*)(XH + (gid + 8) * WPAD + col);
            ah[2] = *(const unsigned*)(XH + gid * WPAD + col + 8);
            ah[3] = *(const unsigned*)(XH + (gid + 8) * WPAD + col + 8);
            al[0] = *(const unsigned*)(XL + gid * WPAD + col);
            al[1] = *(const unsigned*)(XL + (gid + 8) * WPAD + col);
            al[2] = *(const unsigned*)(XL + gid * WPAD + col + 8);
            al[3] = *(const unsigned*)(XL + (gid + 8) * WPAD + col + 8);
#pragma unroll
            for (int nt = 0; nt < 3; nt++) {
                mma_bf16(acc[nt], ah, bhi[nt][kt]);
                mma_bf16(acc[nt], al, bhi[nt][kt]);
                unsigned bl[2];
                const __nv_bfloat16* wl = Wlo + (size_t)(n0 + nt * 8 + gid) * WPAD + col;
                bl[0] = *(const unsigned*)wl;
                bl[1] = *(const unsigned*)(wl + 8);
                mma_bf16(acc[nt], ah, bl);
            }
        }

#pragma unroll
        for (int nt = 0; nt < 3; nt++) {
            const int ccol = n0 + nt * 8 + 2 * tig;
            *(float2*)(HG + gid * HGS + ccol) = make_float2(acc[nt][0], acc[nt][1]);
            *(float2*)(HG + (gid + 8) * HGS + ccol) = make_float2(acc[nt][2], acc[nt][3]);
        }
        __syncthreads();

        {
            float* dst = g_xg + (size_t)tile * 16 * GG;
#pragma unroll
            for (int p = 0; p < 3; p++) {
                int f = tid + p * X_THREADS;
                int col = (f * 4) % GG;
                int row = (f * 4) / GG;
                float4 v = *(const float4*)(HG + row * HGS + col);
                float4 b = *(const float4*)(BS + col);
                v.x += b.x; v.y += b.y; v.z += b.z; v.w += b.w;
                *(float4*)(dst + (size_t)f * 4) = v;
            }
        }
        cp_wait_all();
        __syncthreads();
    }
}

// ---------------------------------------------------------------------------
// Kernel B v2: GRU recurrence, 8 warps x 48-col n-slices, BOTH W_hi and W_lo
// fragments register-resident (192 regs; cap 255 at 256 threads). Per step:
// only A-fragment (h hi/lo) smem traffic remains in the MMA phase.
// ---------------------------------------------------------------------------
#define GM 16                    // batch rows per block
#define G_BLOCKS (BB / GM)       // 64
#define G_THREADS 256            // 8 warps
#define HP 136                   // padded bf16 row stride (h)

#define OFF_HHI 0
#define SZ_HB   (GM * HP * 2)              // 4352
#define OFF_HLO (OFF_HHI + SZ_HB)
#define OFF_HF  (OFF_HLO + SZ_HB)
#define SZ_HF   (GM * HH * 4)              // 8192
#define OFF_HG  (OFF_HF + SZ_HF)
#define SZ_HG   (GM * HGS * 4)             // 24832
#define OFF_XG  (OFF_HG + SZ_HG)
#define SZ_XG   (2 * GM * GG * 4)          // 49152
#define OFF_BS  (OFF_XG + SZ_XG)
#define SZ_BS   (GG * 4)
#define G_SMEM  (OFF_BS + SZ_BS)           // 92416 B

__global__ __launch_bounds__(G_THREADS, 1) void gru_mma_kernel(
    const float* __restrict__ W_hh,
    const float* __restrict__ b_hh)
{
    __nv_bfloat16* Hhi = (__nv_bfloat16*)(g_dsmem + OFF_HHI);
    __nv_bfloat16* Hlo = (__nv_bfloat16*)(g_dsmem + OFF_HLO);
    float* Hf = (float*)(g_dsmem + OFF_HF);
    float* HG = (float*)(g_dsmem + OFF_HG);
    float* XG = (float*)(g_dsmem + OFF_XG);
    float* BS = (float*)(g_dsmem + OFF_BS);

    const int tid = threadIdx.x;
    const int warp = tid >> 5;
    const int lane = tid & 31;
    const int gid = lane >> 2;
    const int tig = lane & 3;
    const int n0 = warp * 48;                // 6 n-tiles per warp
    const int row0 = blockIdx.x * GM;

    for (int i = tid; i < GG; i += G_THREADS) BS[i] = b_hh[i];
    {
        __nv_bfloat16 z = __float2bfloat16(0.f);
        for (int i = tid; i < GM * HP; i += G_THREADS) { Hhi[i] = z; Hlo[i] = z; }
        for (int i = tid; i < GM * HH; i += G_THREADS) Hf[i] = 0.f;
    }

    // stationary W_hi AND W_lo fragments (6 n-tiles x 8 k-tiles x 2 regs each)
    unsigned bhi[6][8][2], blo[6][8][2];
#pragma unroll
    for (int nt = 0; nt < 6; nt++)
#pragma unroll
        for (int kt = 0; kt < 8; kt++) {
            const float* wr = W_hh + (size_t)(n0 + nt * 8 + gid) * HH + kt * 16 + 2 * tig;
            float w0 = wr[0], w1 = wr[1], w8 = wr[8], w9 = wr[9];
            bhi[nt][kt][0] = pack_bf16(w0, w1);
            bhi[nt][kt][1] = pack_bf16(w8, w9);
            blo[nt][kt][0] = pack_bf16(bf16_res(w0), bf16_res(w1));
            blo[nt][kt][1] = pack_bf16(bf16_res(w8), bf16_res(w9));
        }

    const unsigned xg_base = (unsigned)__cvta_generic_to_shared(XG);
    auto stage_xg = [&](int t, int buf) {
        if (t < TT) {
            for (int c = tid; c < GM * GG / 4; c += G_THREADS) {
                int r = c / (GG / 4);
                int off = c % (GG / 4);
                const char* src =
                    (const char*)(g_xg + ((size_t)(row0 + r) * TT + t) * GG) + off * 16;
                cp_async16(xg_base + (unsigned)(buf * GM * GG + r * GG) * 4u + off * 16u, src);
            }
        }
        cp_commit();
    };

    stage_xg(0, 0);
    cp_wait_all();
    __syncthreads();

    const int jj = tid & 127;                // gate-phase column
    const int rb = tid >> 7;                 // gate-phase row base 0..1

    for (int t = 0; t < TT; t++) {
        const int buf = t & 1;
        stage_xg(t + 1, buf ^ 1);

        // --- MMA phase: hg = h @ W^T, 3-product split, all-reg weights ---
        float acc[6][4];
#pragma unroll
        for (int nt = 0; nt < 6; nt++)
#pragma unroll
            for (int i = 0; i < 4; i++) acc[nt][i] = 0.f;

#pragma unroll
        for (int kt = 0; kt < 8; kt++) {
            const int col = kt * 16 + 2 * tig;
            unsigned ah[4], al[4];
            ah[0] = *(const unsigned*)(Hhi + gid * HP + col);
            ah[1] = *(const unsigned*)(Hhi + (gid + 8) * HP + col);
            ah[2] = *(const unsigned*)(Hhi + gid * HP + col + 8);
            ah[3] = *(const unsigned*)(Hhi + (gid + 8) * HP + col + 8);
            al[0] = *(const unsigned*)(Hlo + gid * HP + col);
            al[1] = *(const unsigned*)(Hlo + (gid + 8) * HP + col);
            al[2] = *(const unsigned*)(Hlo + gid * HP + col + 8);
            al[3] = *(const unsigned*)(Hlo + (gid + 8) * HP + col + 8);
#pragma unroll
            for (int nt = 0; nt < 6; nt++) {
                mma_bf16(acc[nt], ah, bhi[nt][kt]);   // hi * hi
                mma_bf16(acc[nt], al, bhi[nt][kt]);   // lo * hi
                mma_bf16(acc[nt], ah, blo[nt][kt]);   // hi * lo
            }
        }

#pragma unroll
        for (int nt = 0; nt < 6; nt++) {
            const int ccol = n0 + nt * 8 + 2 * tig;
            *(float2*)(HG + gid * HGS + ccol) = make_float2(acc[nt][0], acc[nt][1]);
            *(float2*)(HG + (gid + 8) * HGS + ccol) = make_float2(acc[nt][2], acc[nt][3]);
        }
        __syncthreads();

        // --- gate phase: 2048 (r, j) cells over 256 threads ---
        {
            const float* xg = XG + buf * GM * GG;
#pragma unroll
            for (int p = 0; p < 8; p++) {
                const int r = rb + p * 2;
                float pr = HG[r * HGS + jj] + xg[r * GG + jj] + BS[jj];
                float pz = HG[r * HGS + 128 + jj] + xg[r * GG + 128 + jj] + BS[128 + jj];
                float pn = HG[r * HGS + 256 + jj] + BS[256 + jj];
                float rr = sigmoid_fast(pr);
                float zz = sigmoid_fast(pz);
                float nn = tanh_fast(xg[r * GG + 256 + jj] + rr * pn);
                float h = (1.f - zz) * nn + zz * Hf[r * HH + jj];
                Hf[r * HH + jj] = h;
                __nv_bfloat16 hi = __float2bfloat16(h);
                Hhi[r * HP + jj] = hi;
                Hlo[r * HP + jj] = __float2bfloat16(h - __bfloat162float(hi));
            }
        }
        cp_wait_all();
        __syncthreads();
    }

    for (int i = tid; i < GM * HH; i += G_THREADS) {
        int r = i >> 7, j = i & 127;
        g_hT[(size_t)(row0 + r) * HH + j] = Hf[r * HH + j];
    }
}

// ---------------------------------------------------------------------------
// Kernel C: out[b] = W2 . relu(hT[b] @ W1^T + b1) + b2. One warp per row.
// ---------------------------------------------------------------------------
__global__ void head_kernel(
    const float* __restrict__ W1,
    const float* __restrict__ b1,
    const float* __restrict__ W2,
    const float* __restrict__ b2,
    float* __restrict__ out)
{
    const int b = blockIdx.x;
    const int j = threadIdx.x;
    const float* h = g_hT + (size_t)b * HH;

    float acc = 0.f;
#pragma unroll
    for (int k = 0; k < HH; k++)
        acc = fmaf(h[k], W1[j * HH + k], acc);

    float hid = fmaxf(acc + b1[j], 0.f);
    float v = hid * W2[j];
#pragma unroll
    for (int off = 16; off; off >>= 1)
        v += __shfl_xor_sync(0xffffffffu, v, off);
    if (j == 0) out[b] = v + b2[0];
}

// ---------------------------------------------------------------------------
extern "C" void kernel_launch(void* const* d_in, const int* in_sizes, int n_in,
                              void* d_out, int out_size)
{
    const float* x    = (const float*)d_in[0];
    const float* W_ih = (const float*)d_in[1];
    const float* W_hh = (const float*)d_in[2];
    const float* b_ih = (const float*)d_in[3];
    const float* b_hh = (const float*)d_in[4];
    const float* W1   = (const float*)d_in[5];
    const float* b1   = (const float*)d_in[6];
    const float* W2   = (const float*)d_in[7];
    const float* b2   = (const float*)d_in[8];
    float* out        = (float*)d_out;

    cudaFuncSetAttribute(xg_mma_kernel,
                         cudaFuncAttributeMaxDynamicSharedMemorySize, X_SMEM);
    cudaFuncSetAttribute(gru_mma_kernel,
                         cudaFuncAttributeMaxDynamicSharedMemorySize, G_SMEM);

    xg_mma_kernel<<<X_BLOCKS, X_THREADS, X_SMEM>>>(x, W_ih, b_ih);
    gru_mma_kernel<<<G_BLOCKS, G_THREADS, G_SMEM>>>(W_hh, b_hh);
    head_kernel<<<BB, 32>>>(W1, b1, W2, b2, out);
}

// round 15
// speedup vs baseline: 1.1273x; 1.1273x over previous
#include <cuda_runtime.h>
#include <cuda_bf16.h>
#include <math.h>

// Problem dims
#define BB 1024
#define TT 512
#define FF 64
#define HH 128
#define GG 384   // 3*H, gate order (r, z, n)

__device__ __forceinline__ float sigmoid_fast(float x) {
    return __fdividef(1.f, 1.f + __expf(-x));
}
__device__ __forceinline__ float tanh_fast(float x) {
    return 1.f - __fdividef(2.f, __expf(2.f * x) + 1.f);
}

// cp.async helpers (16B)
__device__ __forceinline__ void cp_async16(unsigned int smem_addr, const void* gptr) {
    asm volatile("cp.async.cg.shared.global [%0], [%1], 16;" :: "r"(smem_addr), "l"(gptr));
}
__device__ __forceinline__ void cp_commit() {
    asm volatile("cp.async.commit_group;");
}
__device__ __forceinline__ void cp_wait_all() {
    asm volatile("cp.async.wait_group 0;" ::: "memory");
}

// bf16 mma m16n8k16 row.col, f32 accumulate
__device__ __forceinline__ void mma_bf16(float* c, const unsigned* a, const unsigned* b) {
    asm volatile(
        "mma.sync.aligned.m16n8k16.row.col.f32.bf16.bf16.f32 "
        "{%0,%1,%2,%3}, {%4,%5,%6,%7}, {%8,%9}, {%0,%1,%2,%3};"
        : "+f"(c[0]), "+f"(c[1]), "+f"(c[2]), "+f"(c[3])
        : "r"(a[0]), "r"(a[1]), "r"(a[2]), "r"(a[3]), "r"(b[0]), "r"(b[1]));
}

__device__ __forceinline__ unsigned pack_bf16(float f0, float f1) {
    unsigned short u0 = __bfloat16_as_ushort(__float2bfloat16(f0));
    unsigned short u1 = __bfloat16_as_ushort(__float2bfloat16(f1));
    return (unsigned)u0 | ((unsigned)u1 << 16);
}

__device__ __forceinline__ float bf16_res(float v) {   // v - bf16(v)
    return v - __bfloat162float(__float2bfloat16(v));
}

// Scratch (allocation-free rule: __device__ globals)
__device__ float g_xg[(size_t)BB * TT * GG];  // [B*T, 3H] input-side pre-acts (includes b_ih)
__device__ float g_hT[BB * HH];               // final hidden state

extern __shared__ __align__(16) char g_dsmem[];

#define HGS 388                  // padded f32 row stride (frag-store tiles)

// ---------------------------------------------------------------------------
// Kernel A v2: xg = x @ W_ih^T + b_ih on tensor cores.
// 296 blocks x 256 threads (8 warps, n-slice 48) -> 2 blocks/SM so the
// per-tile serial chain (convert -> MMA -> writeout) of one block overlaps
// the other's. Grid-stride over 32768 bt-tiles of 16 rows.
// ---------------------------------------------------------------------------
#define XNT (BB * TT / 16)       // 32768 tiles
#define X_THREADS 256
#define X_BLOCKS 296
#define WPAD 72                  // padded bf16 K-stride

#define X_OFF_WLO 0
#define X_SZ_WLO  (GG * WPAD * 2)           // 55296
#define X_OFF_XF  (X_OFF_WLO + X_SZ_WLO)
#define X_SZ_XF   (2 * 16 * FF * 4)         // 8192
#define X_OFF_XHI (X_OFF_XF + X_SZ_XF)
#define X_SZ_XB   (2 * 16 * WPAD * 2)       // 4608
#define X_OFF_XLO (X_OFF_XHI + X_SZ_XB)
#define X_OFF_HG  (X_OFF_XLO + X_SZ_XB)
#define X_SZ_HG   (16 * HGS * 4)            // 24832
#define X_OFF_BS  (X_OFF_HG + X_SZ_HG)
#define X_SZ_BS   (GG * 4)
#define X_SMEM    (X_OFF_BS + X_SZ_BS)      // 99072 B (x2 blocks = 198144 <= 228KB/SM)

__global__ __launch_bounds__(X_THREADS, 2) void xg_mma_kernel(
    const float* __restrict__ x,
    const float* __restrict__ W_ih,
    const float* __restrict__ b_ih)
{
    __nv_bfloat16* Wlo = (__nv_bfloat16*)(g_dsmem + X_OFF_WLO);
    float* Xf = (float*)(g_dsmem + X_OFF_XF);
    __nv_bfloat16* Xhi = (__nv_bfloat16*)(g_dsmem + X_OFF_XHI);
    __nv_bfloat16* Xlo = (__nv_bfloat16*)(g_dsmem + X_OFF_XLO);
    float* HG = (float*)(g_dsmem + X_OFF_HG);
    float* BS = (float*)(g_dsmem + X_OFF_BS);

    const int tid = threadIdx.x;
    const int warp = tid >> 5;               // 0..7
    const int lane = tid & 31;
    const int gid = lane >> 2;
    const int tig = lane & 3;
    const int n0 = warp * 48;                // 6 n-tiles per warp

    for (int i = tid; i < GG * FF; i += X_THREADS) {
        int n = i >> 6, k = i & 63;
        float w = W_ih[i];
        Wlo[n * WPAD + k] = __float2bfloat16(bf16_res(w));
    }
    for (int i = tid; i < GG; i += X_THREADS) BS[i] = b_ih[i];

    // stationary W_hi fragments (6 n-tiles x 4 k-tiles)
    unsigned bhi[6][4][2];
#pragma unroll
    for (int nt = 0; nt < 6; nt++)
#pragma unroll
        for (int kt = 0; kt < 4; kt++) {
            const float* wr = W_ih + (size_t)(n0 + nt * 8 + gid) * FF + kt * 16 + 2 * tig;
            bhi[nt][kt][0] = pack_bf16(wr[0], wr[1]);
            bhi[nt][kt][1] = pack_bf16(wr[8], wr[9]);
        }

    const unsigned xf_base = (unsigned)__cvta_generic_to_shared(Xf);
    auto stage = [&](int tile, int buf) {
        if (tile < XNT)
            cp_async16(xf_base + (unsigned)buf * 4096u + (unsigned)tid * 16u,
                       (const char*)x + (size_t)tile * 4096 + (size_t)tid * 16);
        cp_commit();
    };

    stage(blockIdx.x, 0);
    cp_wait_all();
    __syncthreads();

    int it = 0;
    for (int tile = blockIdx.x; tile < XNT; tile += gridDim.x, it++) {
        const int buf = it & 1;
        stage(tile + gridDim.x, buf ^ 1);

        // convert x tile fp32 -> bf16 hi/lo (4 elems per thread)
        for (int i = tid; i < 16 * FF; i += X_THREADS) {
            int r = i >> 6, c = i & 63;
            float v = Xf[buf * 1024 + i];
            __nv_bfloat16 hi = __float2bfloat16(v);
            Xhi[buf * 16 * WPAD + r * WPAD + c] = hi;
            Xlo[buf * 16 * WPAD + r * WPAD + c] =
                __float2bfloat16(v - __bfloat162float(hi));
        }
        __syncthreads();

        float acc[6][4];
#pragma unroll
        for (int nt = 0; nt < 6; nt++)
#pragma unroll
            for (int i = 0; i < 4; i++) acc[nt][i] = 0.f;

        const __nv_bfloat16* XH = Xhi + buf * 16 * WPAD;
        const __nv_bfloat16* XL = Xlo + buf * 16 * WPAD;
#pragma unroll
        for (int kt = 0; kt < 4; kt++) {
            const int col = kt * 16 + 2 * tig;
            unsigned ah[4], al[4];
            ah[0] = *(const unsigned*)(XH + gid * WPAD + col);
            ah[1] = *(const unsigned*)(XH + (gid + 8) * WPAD + col);
            ah[2] = *(const unsigned*)(XH + gid * WPAD + col + 8);
            ah[3] = *(const unsigned*)(XH + (gid + 8) * WPAD + col + 8);
            al[0] = *(const unsigned*)(XL + gid * WPAD + col);
            al[1] = *(const unsigned*)(XL + (gid + 8) * WPAD + col);
            al[2] = *(const unsigned*)(XL + gid * WPAD + col + 8);
            al[3] = *(const unsigned*)(XL + (gid + 8) * WPAD + col + 8);
#pragma unroll
            for (int nt = 0; nt < 6; nt++) {
                mma_bf16(acc[nt], ah, bhi[nt][kt]);   // hi * hi
                mma_bf16(acc[nt], al, bhi[nt][kt]);   // lo * hi
                unsigned bl[2];
                const __nv_bfloat16* wl = Wlo + (size_t)(n0 + nt * 8 + gid) * WPAD + col;
                bl[0] = *(const unsigned*)wl;
                bl[1] = *(const unsigned*)(wl + 8);
                mma_bf16(acc[nt], ah, bl);            // hi * lo
            }
        }

#pragma unroll
        for (int nt = 0; nt < 6; nt++) {
            const int ccol = n0 + nt * 8 + 2 * tig;
            *(float2*)(HG + gid * HGS + ccol) = make_float2(acc[nt][0], acc[nt][1]);
            *(float2*)(HG + (gid + 8) * HGS + ccol) = make_float2(acc[nt][2], acc[nt][3]);
        }
        __syncthreads();

        // coalesced write-out with bias (16x384 contiguous; 6 float4/thread)
        {
            float* dst = g_xg + (size_t)tile * 16 * GG;
#pragma unroll
            for (int p = 0; p < 6; p++) {
                int f = tid + p * X_THREADS;
                int col = (f * 4) % GG;
                int row = (f * 4) / GG;
                float4 v = *(const float4*)(HG + row * HGS + col);
                float4 b = *(const float4*)(BS + col);
                v.x += b.x; v.y += b.y; v.z += b.z; v.w += b.w;
                *(float4*)(dst + (size_t)f * 4) = v;
            }
        }
        cp_wait_all();
        __syncthreads();
    }
}

// ---------------------------------------------------------------------------
// Kernel B: GRU recurrence on tensor cores — EXACT revert to the R8/R9
// passing config (16 warps x 24-col slices, W_hi in regs, W_lo in smem,
// measured ~1343 us). The 8-warp all-reg variant regressed; do not reapply.
// ---------------------------------------------------------------------------
#define GM 16                    // batch rows per block
#define G_BLOCKS (BB / GM)       // 64
#define G_THREADS 512            // 16 warps
#define NSLICE 24                // gate cols per warp
#define HP 136                   // padded bf16 row stride (h, W_lo)

#define OFF_WLO 0
#define SZ_WLO  (GG * HP * 2)              // 104448
#define OFF_HHI (OFF_WLO + SZ_WLO)
#define SZ_HB   (GM * HP * 2)              // 4352
#define OFF_HLO (OFF_HHI + SZ_HB)
#define OFF_HF  (OFF_HLO + SZ_HB)
#define SZ_HF   (GM * HH * 4)              // 8192
#define OFF_HG  (OFF_HF + SZ_HF)
#define SZ_HG   (GM * HGS * 4)             // 24832
#define OFF_XG  (OFF_HG + SZ_HG)
#define SZ_XG   (2 * GM * GG * 4)          // 49152
#define OFF_BS  (OFF_XG + SZ_XG)
#define SZ_BS   (GG * 4)
#define G_SMEM  (OFF_BS + SZ_BS)           // 196864 B

__global__ __launch_bounds__(G_THREADS, 1) void gru_mma_kernel(
    const float* __restrict__ W_hh,
    const float* __restrict__ b_hh)
{
    __nv_bfloat16* Wlo = (__nv_bfloat16*)(g_dsmem + OFF_WLO);
    __nv_bfloat16* Hhi = (__nv_bfloat16*)(g_dsmem + OFF_HHI);
    __nv_bfloat16* Hlo = (__nv_bfloat16*)(g_dsmem + OFF_HLO);
    float* Hf = (float*)(g_dsmem + OFF_HF);
    float* HG = (float*)(g_dsmem + OFF_HG);
    float* XG = (float*)(g_dsmem + OFF_XG);
    float* BS = (float*)(g_dsmem + OFF_BS);

    const int tid = threadIdx.x;
    const int warp = tid >> 5;
    const int lane = tid & 31;
    const int gid = lane >> 2;
    const int tig = lane & 3;
    const int n0 = warp * NSLICE;
    const int row0 = blockIdx.x * GM;

    for (int i = tid; i < GG * HH; i += G_THREADS) {
        int n = i >> 7, k = i & 127;
        float w = W_hh[i];
        __nv_bfloat16 hi = __float2bfloat16(w);
        Wlo[n * HP + k] = __float2bfloat16(w - __bfloat162float(hi));
    }
    for (int i = tid; i < GG; i += G_THREADS) BS[i] = b_hh[i];
    {
        __nv_bfloat16 z = __float2bfloat16(0.f);
        for (int i = tid; i < GM * HP; i += G_THREADS) { Hhi[i] = z; Hlo[i] = z; }
        for (int i = tid; i < GM * HH; i += G_THREADS) Hf[i] = 0.f;
    }

    unsigned bhi[3][8][2];
#pragma unroll
    for (int nt = 0; nt < 3; nt++)
#pragma unroll
        for (int kt = 0; kt < 8; kt++) {
            const float* wr = W_hh + (size_t)(n0 + nt * 8 + gid) * HH + kt * 16 + 2 * tig;
            bhi[nt][kt][0] = pack_bf16(wr[0], wr[1]);
            bhi[nt][kt][1] = pack_bf16(wr[8], wr[9]);
        }

    const unsigned xg_base = (unsigned)__cvta_generic_to_shared(XG);
    auto stage_xg = [&](int t, int buf) {
        if (t < TT) {
            for (int c = tid; c < GM * GG / 4; c += G_THREADS) {
                int r = c / (GG / 4);
                int off = c % (GG / 4);
                const char* src =
                    (const char*)(g_xg + ((size_t)(row0 + r) * TT + t) * GG) + off * 16;
                cp_async16(xg_base + (unsigned)(buf * GM * GG + r * GG) * 4u + off * 16u, src);
            }
        }
        cp_commit();
    };

    stage_xg(0, 0);
    cp_wait_all();
    __syncthreads();

    const int jj = tid & 127;
    const int rb = tid >> 7;

    for (int t = 0; t < TT; t++) {
        const int buf = t & 1;
        stage_xg(t + 1, buf ^ 1);

        float acc[3][4];
#pragma unroll
        for (int nt = 0; nt < 3; nt++)
#pragma unroll
            for (int i = 0; i < 4; i++) acc[nt][i] = 0.f;

#pragma unroll
        for (int kt = 0; kt < 8; kt++) {
            const int col = kt * 16 + 2 * tig;
            unsigned ah[4], al[4];
            ah[0] = *(const unsigned*)(Hhi + gid * HP + col);
            ah[1] = *(const unsigned*)(Hhi + (gid + 8) * HP + col);
            ah[2] = *(const unsigned*)(Hhi + gid * HP + col + 8);
            ah[3] = *(const unsigned*)(Hhi + (gid + 8) * HP + col + 8);
            al[0] = *(const unsigned*)(Hlo + gid * HP + col);
            al[1] = *(const unsigned*)(Hlo + (gid + 8) * HP + col);
            al[2] = *(const unsigned*)(Hlo + gid * HP + col + 8);
            al[3] = *(const unsigned*)(Hlo + (gid + 8) * HP + col + 8);
#pragma unroll
            for (int nt = 0; nt < 3; nt++) {
                mma_bf16(acc[nt], ah, bhi[nt][kt]);
                mma_bf16(acc[nt], al, bhi[nt][kt]);
                unsigned bl[2];
                const __nv_bfloat16* wl = Wlo + (size_t)(n0 + nt * 8 + gid) * HP + col;
                bl[0] = *(const unsigned*)wl;
                bl[1] = *(const unsigned*)(wl + 8);
                mma_bf16(acc[nt], ah, bl);
            }
        }

#pragma unroll
        for (int nt = 0; nt < 3; nt++) {
            const int ccol = n0 + nt * 8 + 2 * tig;
            *(float2*)(HG + gid * HGS + ccol) = make_float2(acc[nt][0], acc[nt][1]);
            *(float2*)(HG + (gid + 8) * HGS + ccol) = make_float2(acc[nt][2], acc[nt][3]);
        }
        __syncthreads();

        {
            const float* xg = XG + buf * GM * GG;
#pragma unroll
            for (int p = 0; p < 4; p++) {
                const int r = rb + p * 4;
                float pr = HG[r * HGS + jj] + xg[r * GG + jj] + BS[jj];
                float pz = HG[r * HGS + 128 + jj] + xg[r * GG + 128 + jj] + BS[128 + jj];
                float pn = HG[r * HGS + 256 + jj] + BS[256 + jj];
                float rr = sigmoid_fast(pr);
                float zz = sigmoid_fast(pz);
                float nn = tanh_fast(xg[r * GG + 256 + jj] + rr * pn);
                float h = (1.f - zz) * nn + zz * Hf[r * HH + jj];
                Hf[r * HH + jj] = h;
                __nv_bfloat16 hi = __float2bfloat16(h);
                Hhi[r * HP + jj] = hi;
                Hlo[r * HP + jj] = __float2bfloat16(h - __bfloat162float(hi));
            }
        }
        cp_wait_all();
        __syncthreads();
    }

    for (int i = tid; i < GM * HH; i += G_THREADS) {
        int r = i >> 7, j = i & 127;
        g_hT[(size_t)(row0 + r) * HH + j] = Hf[r * HH + j];
    }
}

// ---------------------------------------------------------------------------
// Kernel C: out[b] = W2 . relu(hT[b] @ W1^T + b1) + b2. One warp per row.
// ---------------------------------------------------------------------------
__global__ void head_kernel(
    const float* __restrict__ W1,
    const float* __restrict__ b1,
    const float* __restrict__ W2,
    const float* __restrict__ b2,
    float* __restrict__ out)
{
    const int b = blockIdx.x;
    const int j = threadIdx.x;
    const float* h = g_hT + (size_t)b * HH;

    float acc = 0.f;
#pragma unroll
    for (int k = 0; k < HH; k++)
        acc = fmaf(h[k], W1[j * HH + k], acc);

    float hid = fmaxf(acc + b1[j], 0.f);
    float v = hid * W2[j];
#pragma unroll
    for (int off = 16; off; off >>= 1)
        v += __shfl_xor_sync(0xffffffffu, v, off);
    if (j == 0) out[b] = v + b2[0];
}

// ---------------------------------------------------------------------------
extern "C" void kernel_launch(void* const* d_in, const int* in_sizes, int n_in,
                              void* d_out, int out_size)
{
    const float* x    = (const float*)d_in[0];
    const float* W_ih = (const float*)d_in[1];
    const float* W_hh = (const float*)d_in[2];
    const float* b_ih = (const float*)d_in[3];
    const float* b_hh = (const float*)d_in[4];
    const float* W1   = (const float*)d_in[5];
    const float* b1   = (const float*)d_in[6];
    const float* W2   = (const float*)d_in[7];
    const float* b2   = (const float*)d_in[8];
    float* out        = (float*)d_out;

    cudaFuncSetAttribute(xg_mma_kernel,
                         cudaFuncAttributeMaxDynamicSharedMemorySize, X_SMEM);
    cudaFuncSetAttribute(gru_mma_kernel,
                         cudaFuncAttributeMaxDynamicSharedMemorySize, G_SMEM);

    xg_mma_kernel<<<X_BLOCKS, X_THREADS, X_SMEM>>>(x, W_ih, b_ih);
    gru_mma_kernel<<<G_BLOCKS, G_THREADS, G_SMEM>>>(W_hh, b_hh);
    head_kernel<<<BB, 32>>>(W1, b1, W2, b2, out);
}